// round 14
// baseline (speedup 1.0000x reference)
#include <cuda_runtime.h>
#include <cstdint>

#define BATCH     512
#define SIZE_IN   1024
#define SIZE_OUT  256
#define NQ        16

#define BT        64                 // batch tile per CTA
#define ISPLIT    37                 // 8 * 37 = 296 = 148 SMs * 2 CTAs exactly
#define NPHMAX    14                 // ceil(28/2)
#define NTHREADS  512
#define SLOT_B    32768              // bytes per ring slot (2 features x 16 rows x 1 KB fp32)
#define RING_B    (3 * SLOT_B)       // 96 KB dynamic smem

// out[b,o] = bias[o]  (atomic accumulation target)
__global__ void il_init_out(const float* __restrict__ bias, float* __restrict__ out) {
    out[blockIdx.x * SIZE_OUT + threadIdx.x] = bias[threadIdx.x];
}

__device__ __forceinline__ void cp_async16(uint32_t saddr, const void* gptr) {
    asm volatile("cp.async.cg.shared.global [%0], [%1], 16;\n" :: "r"(saddr), "l"(gptr));
}
__device__ __forceinline__ void cp_commit() {
    asm volatile("cp.async.commit_group;\n" ::: "memory");
}
__device__ __forceinline__ void red_v4(float* p, float a, float b, float c, float d) {
    asm volatile("red.global.add.v4.f32 [%0], {%1, %2, %3, %4};"
                 :: "l"(p), "f"(a), "f"(b), "f"(c), "f"(d) : "memory");
}

// One CTA: 64 batches x (27..28) features x 256 outputs, fp32 weights.
// Ring-3 of 32 KB phase buffers (2 features each); one cp.async commit group
// per phase, wait_group 1 keeps a full phase of prefetch in flight.
__global__ __launch_bounds__(NTHREADS, 2)
void il_main(const float* __restrict__ x,
             const int* __restrict__ indices,   // JAX canonicalizes int64 -> int32
             const float* __restrict__ table,
             float* __restrict__ out) {
    extern __shared__ __align__(16) float sW[];   // 3 x 8192 floats (96 KB)
    __shared__ float4 sxq[BT][NPHMAX];   // {x0, bits(q0*256), x1, bits(q1*256)}

    const int b0  = blockIdx.x * BT;
    const int lo  = (int)(((long long)blockIdx.y * SIZE_IN) / ISPLIT);
    const int hi  = (int)(((long long)(blockIdx.y + 1) * SIZE_IN) / ISPLIT);
    const int len = hi - lo;             // 27 or 28
    const int nph = (len + 1) >> 1;      // 14
    const int t   = threadIdx.x;
    const int og  = t & 31;              // output columns og*8 .. og*8+7
    const int bg  = t >> 5;              // batches bg*4 .. bg*4+3 (warp-uniform)

    const uint32_t sW_u32 = (uint32_t)__cvta_generic_to_shared(sW);
    const int sq = t >> 5;               // staged row 0..15
    const int sc = t & 31;               // 16B chunk within the first 512 B of the row
    const uint32_t lane_off = (uint32_t)(sq * 1024 + sc * 16);
    const float* src_base = table + ((size_t)sq * SIZE_IN) * SIZE_OUT + sc * 4;

    // Prefetch phases 0 and 1 (slots 0, 1), one commit group each.
    #pragma unroll
    for (int p0 = 0; p0 < 2; p0++) {
        if (p0 < nph) {
            const int i0 = lo + 2 * p0;
            const uint32_t dst = sW_u32 + (uint32_t)p0 * SLOT_B + lane_off;
            const float* src = src_base + (size_t)i0 * SIZE_OUT;
            cp_async16(dst, src);                       // feature i0, first half-row
            cp_async16(dst + 512u, src + 128);          // feature i0, second half-row
            if (i0 + 1 < hi) {
                cp_async16(dst + 16384u, src + SIZE_OUT);         // feature i0+1
                cp_async16(dst + 16896u, src + SIZE_OUT + 128);
            }
        }
        cp_commit();
    }

    // Preload sxq: thread covers batch bl = t>>3, phases (t&7) + 8k.
    {
        const int bl = t >> 3;
        const float* xp = x       + (size_t)(b0 + bl) * SIZE_IN;
        const int*   qp = indices + (size_t)(b0 + bl) * SIZE_IN;
        #pragma unroll
        for (int k = 0; k < 2; k++) {
            const int p = (t & 7) + k * 8;
            if (p < nph) {
                const int i0 = lo + 2 * p;
                float4 v;
                v.x = xp[i0];
                v.y = __int_as_float(qp[i0] * SIZE_OUT);
                if (i0 + 1 < hi) {
                    v.z = xp[i0 + 1];
                    v.w = __int_as_float(qp[i0 + 1] * SIZE_OUT);
                } else {
                    v.z = 0.f;
                    v.w = __int_as_float(0);
                }
                sxq[bl][p] = v;
            }
        }
    }

    float acc[4][8];
    #pragma unroll
    for (int bl = 0; bl < 4; bl++)
        #pragma unroll
        for (int c = 0; c < 8; c++) acc[bl][c] = 0.f;

    uint32_t curB = 0;   // byte offset of slot p%3: cycles 0, 32768, 65536
    for (int p = 0; p < nph; p++) {
        // Retire this phase's group; keep the next phase's group in flight.
        if (p + 1 < nph) asm volatile("cp.async.wait_group 1;" ::: "memory");
        else             asm volatile("cp.async.wait_group 0;" ::: "memory");
        __syncthreads();   // staged data visible; all readers done with slot (p+2)%3

        // Prefetch phase p+2 into slot (p+2)%3 (just freed).
        if (p + 2 < nph) {
            const int i0 = lo + 2 * (p + 2);
            uint32_t nextB = curB + 2u * SLOT_B;
            if (nextB >= RING_B) nextB -= RING_B;
            const uint32_t dst = sW_u32 + nextB + lane_off;
            const float* src = src_base + (size_t)i0 * SIZE_OUT;
            cp_async16(dst, src);
            cp_async16(dst + 512u, src + 128);
            if (i0 + 1 < hi) {
                cp_async16(dst + 16384u, src + SIZE_OUT);
                cp_async16(dst + 16896u, src + SIZE_OUT + 128);
            }
            cp_commit();
        }

        const float* wb  = sW + (curB >> 2);   // curB bytes -> floats
        const bool    two = (2 * p + 1 < len);

        float4 v[4];
        #pragma unroll
        for (int bl = 0; bl < 4; bl++) v[bl] = sxq[bg * 4 + bl][p];   // 16B broadcast

        // feature 0 of the phase
        #pragma unroll
        for (int bl = 0; bl < 4; bl++) {
            const float* wp = wb + __float_as_int(v[bl].y) + og * 8;
            const float4 u0 = *reinterpret_cast<const float4*>(wp);
            const float4 u1 = *reinterpret_cast<const float4*>(wp + 4);
            acc[bl][0] += v[bl].x * u0.x;  acc[bl][1] += v[bl].x * u0.y;
            acc[bl][2] += v[bl].x * u0.z;  acc[bl][3] += v[bl].x * u0.w;
            acc[bl][4] += v[bl].x * u1.x;  acc[bl][5] += v[bl].x * u1.y;
            acc[bl][6] += v[bl].x * u1.z;  acc[bl][7] += v[bl].x * u1.w;
        }
        // feature 1 of the phase
        if (two) {
            #pragma unroll
            for (int bl = 0; bl < 4; bl++) {
                const float* wp = wb + 4096 + __float_as_int(v[bl].w) + og * 8;
                const float4 u0 = *reinterpret_cast<const float4*>(wp);
                const float4 u1 = *reinterpret_cast<const float4*>(wp + 4);
                acc[bl][0] += v[bl].z * u0.x;  acc[bl][1] += v[bl].z * u0.y;
                acc[bl][2] += v[bl].z * u0.z;  acc[bl][3] += v[bl].z * u0.w;
                acc[bl][4] += v[bl].z * u1.x;  acc[bl][5] += v[bl].z * u1.y;
                acc[bl][6] += v[bl].z * u1.z;  acc[bl][7] += v[bl].z * u1.w;
            }
        }

        curB += SLOT_B;
        if (curB == RING_B) curB = 0;
    }

    // Combine split-k partials: 2 vectorized reductions per batch.
    #pragma unroll
    for (int bl = 0; bl < 4; bl++) {
        const int b = b0 + bg * 4 + bl;
        float* op = out + (size_t)b * SIZE_OUT + og * 8;
        red_v4(op,     acc[bl][0], acc[bl][1], acc[bl][2], acc[bl][3]);
        red_v4(op + 4, acc[bl][4], acc[bl][5], acc[bl][6], acc[bl][7]);
    }
}

extern "C" void kernel_launch(void* const* d_in, const int* in_sizes, int n_in,
                              void* d_out, int out_size) {
    const float* x       = (const float*)d_in[0];
    const int*   indices = (const int*)d_in[1];
    const float* table   = (const float*)d_in[2];
    const float* bias    = (const float*)d_in[3];
    float*       out     = (float*)d_out;

    static int attr_set = 0;
    if (!attr_set) {
        cudaFuncSetAttribute(il_main, cudaFuncAttributeMaxDynamicSharedMemorySize, RING_B);
        attr_set = 1;
    }

    il_init_out<<<BATCH, SIZE_OUT>>>(bias, out);

    dim3 grid(BATCH / BT, ISPLIT);   // 8 x 37 = 296 CTAs = 148 SMs * 2
    il_main<<<grid, NTHREADS, RING_B>>>(x, indices, table, out);
}

// round 15
// speedup vs baseline: 1.6511x; 1.6511x over previous
#include <cuda_runtime.h>
#include <cuda_fp16.h>
#include <cstdint>

#define BATCH     512
#define SIZE_IN   1024
#define SIZE_OUT  256
#define NQ        16

#define BT        32                 // batch tile per CTA
#define ISPLIT    37                 // 16 * 37 = 592 = 148 SMs * 4 CTAs exactly
#define NPHMAX    14                 // ceil(28/2)
#define NTHREADS  256
#define SLOT_B    16384              // bytes per slot: 2 features x 16 rows x 512 B fp16
#define RING_B    (2 * SLOT_B)       // 32 KB dynamic smem (double buffer)

// fp16 copy of the weight table (8 MB static scratch; no allocation allowed)
__device__ __half g_tableh[NQ * SIZE_IN * SIZE_OUT];

// Fused prep: table fp32 -> fp16, 4 elems/thread (1 LDG.128 + 1 STG.64),
// 1M threads for max MLP; first 512 blocks also write out[b,:] = bias.
__global__ void il_prep(const float* __restrict__ table,
                        const float* __restrict__ bias,
                        float* __restrict__ out) {
    const size_t i = ((size_t)blockIdx.x * NTHREADS + threadIdx.x) * 4;
    const float4 a = *reinterpret_cast<const float4*>(table + i);
    __half2 h[2];
    h[0] = __floats2half2_rn(a.x, a.y);
    h[1] = __floats2half2_rn(a.z, a.w);
    *reinterpret_cast<uint2*>(g_tableh + i) = *reinterpret_cast<uint2*>(h);

    if (blockIdx.x < BATCH) {   // out[b, o] = bias[o]  (256 threads = 256 outputs)
        out[blockIdx.x * SIZE_OUT + threadIdx.x] = bias[threadIdx.x];
    }
}

__device__ __forceinline__ void cp_async16(uint32_t saddr, const void* gptr) {
    asm volatile("cp.async.cg.shared.global [%0], [%1], 16;\n" :: "r"(saddr), "l"(gptr));
}
__device__ __forceinline__ void cp_commit() {
    asm volatile("cp.async.commit_group;\n" ::: "memory");
}
__device__ __forceinline__ void red_v4(float* p, float a, float b, float c, float d) {
    asm volatile("red.global.add.v4.f32 [%0], {%1, %2, %3, %4};"
                 :: "l"(p), "f"(a), "f"(b), "f"(c), "f"(d) : "memory");
}

// One CTA: 32 batches x (27..28) features x 256 outputs, fp16 weights.
// 4 CTAs/SM for latency hiding; double-buffered 16 KB phases (2 features each).
__global__ __launch_bounds__(NTHREADS, 4)
void il_main(const float* __restrict__ x,
             const int* __restrict__ indices,   // JAX canonicalizes int64 -> int32
             float* __restrict__ out) {
    extern __shared__ __align__(16) __half sW[];   // 2 x 8192 halves (32 KB)
    __shared__ float4 sxq[BT][NPHMAX];   // {x0, bits(q0*256), x1, bits(q1*256)}

    const int b0  = blockIdx.x * BT;
    const int lo  = (int)(((long long)blockIdx.y * SIZE_IN) / ISPLIT);
    const int hi  = (int)(((long long)(blockIdx.y + 1) * SIZE_IN) / ISPLIT);
    const int len = hi - lo;             // 27 or 28
    const int nph = (len + 1) >> 1;      // 14
    const int t   = threadIdx.x;
    const int og  = t & 31;              // output columns og*8 .. og*8+7
    const int bg  = t >> 5;              // batches bg*4 .. bg*4+3 (warp-uniform)

    const uint32_t sW_u32 = (uint32_t)__cvta_generic_to_shared(sW);

    // Staging map: per feature, thread covers segments t and t+256 (512 x 16B total).
    // seg -> row q = seg>>5, 16B chunk c = seg&31.
    const int q0 = t >> 5, c0 = t & 31;          // seg = t
    const int q1 = (t + 256) >> 5, c1 = t & 31;  // seg = t + 256
    const uint32_t off0 = (uint32_t)(q0 * 512 + c0 * 16);
    const uint32_t off1 = (uint32_t)(q1 * 512 + c1 * 16);
    const __half* sb0 = g_tableh + ((size_t)q0 * SIZE_IN) * SIZE_OUT + c0 * 8;
    const __half* sb1 = g_tableh + ((size_t)q1 * SIZE_IN) * SIZE_OUT + c1 * 8;

    // Prefetch phase 0 into buffer 0 (one commit group).
    {
        const int i0 = lo;
        cp_async16(sW_u32 + off0, sb0 + (size_t)i0 * SIZE_OUT);
        cp_async16(sW_u32 + off1, sb1 + (size_t)i0 * SIZE_OUT);
        if (i0 + 1 < hi) {
            cp_async16(sW_u32 + 8192u + off0, sb0 + (size_t)(i0 + 1) * SIZE_OUT);
            cp_async16(sW_u32 + 8192u + off1, sb1 + (size_t)(i0 + 1) * SIZE_OUT);
        }
        cp_commit();
    }

    // Preload sxq: thread covers batch bl = t>>3, phases (t&7) + 8k.
    {
        const int bl = t >> 3;
        const float* xp = x       + (size_t)(b0 + bl) * SIZE_IN;
        const int*   qp = indices + (size_t)(b0 + bl) * SIZE_IN;
        #pragma unroll
        for (int k = 0; k < 2; k++) {
            const int p = (t & 7) + k * 8;
            if (p < nph) {
                const int i0 = lo + 2 * p;
                float4 v;
                v.x = xp[i0];
                v.y = __int_as_float(qp[i0] * SIZE_OUT);
                if (i0 + 1 < hi) {
                    v.z = xp[i0 + 1];
                    v.w = __int_as_float(qp[i0 + 1] * SIZE_OUT);
                } else {
                    v.z = 0.f;
                    v.w = __int_as_float(0);
                }
                sxq[bl][p] = v;
            }
        }
    }

    float acc[4][8];
    #pragma unroll
    for (int bl = 0; bl < 4; bl++)
        #pragma unroll
        for (int c = 0; c < 8; c++) acc[bl][c] = 0.f;

    for (int p = 0; p < nph; p++) {
        const int buf = p & 1;

        asm volatile("cp.async.wait_group 0;" ::: "memory");
        __syncthreads();   // staged data visible; all readers done with buf^1

        // Prefetch phase p+1 into the other buffer.
        if (p + 1 < nph) {
            const int i0 = lo + 2 * (p + 1);
            const uint32_t dst = sW_u32 + (uint32_t)((buf ^ 1) * SLOT_B);
            cp_async16(dst + off0, sb0 + (size_t)i0 * SIZE_OUT);
            cp_async16(dst + off1, sb1 + (size_t)i0 * SIZE_OUT);
            if (i0 + 1 < hi) {
                cp_async16(dst + 8192u + off0, sb0 + (size_t)(i0 + 1) * SIZE_OUT);
                cp_async16(dst + 8192u + off1, sb1 + (size_t)(i0 + 1) * SIZE_OUT);
            }
            cp_commit();
        }

        const __half* wb  = sW + buf * 8192;
        const bool    two = (2 * p + 1 < len);

        float4 v[4];
        #pragma unroll
        for (int bl = 0; bl < 4; bl++) v[bl] = sxq[bg * 4 + bl][p];   // 16B broadcast

        // feature 0 of the phase
        #pragma unroll
        for (int bl = 0; bl < 4; bl++) {
            const uint4 u = *reinterpret_cast<const uint4*>(
                wb + __float_as_int(v[bl].y) + og * 8);
            const __half2* hp = reinterpret_cast<const __half2*>(&u);
            #pragma unroll
            for (int q = 0; q < 4; q++) {
                const float2 f = __half22float2(hp[q]);
                acc[bl][q * 2 + 0] += v[bl].x * f.x;
                acc[bl][q * 2 + 1] += v[bl].x * f.y;
            }
        }
        // feature 1 of the phase
        if (two) {
            #pragma unroll
            for (int bl = 0; bl < 4; bl++) {
                const uint4 u = *reinterpret_cast<const uint4*>(
                    wb + 4096 + __float_as_int(v[bl].w) + og * 8);
                const __half2* hp = reinterpret_cast<const __half2*>(&u);
                #pragma unroll
                for (int q = 0; q < 4; q++) {
                    const float2 f = __half22float2(hp[q]);
                    acc[bl][q * 2 + 0] += v[bl].z * f.x;
                    acc[bl][q * 2 + 1] += v[bl].z * f.y;
                }
            }
        }
    }

    // Combine split-k partials: 2 vectorized reductions per batch.
    #pragma unroll
    for (int bl = 0; bl < 4; bl++) {
        const int b = b0 + bg * 4 + bl;
        float* op = out + (size_t)b * SIZE_OUT + og * 8;
        red_v4(op,     acc[bl][0], acc[bl][1], acc[bl][2], acc[bl][3]);
        red_v4(op + 4, acc[bl][4], acc[bl][5], acc[bl][6], acc[bl][7]);
    }
}

extern "C" void kernel_launch(void* const* d_in, const int* in_sizes, int n_in,
                              void* d_out, int out_size) {
    const float* x       = (const float*)d_in[0];
    const int*   indices = (const int*)d_in[1];
    const float* table   = (const float*)d_in[2];
    const float* bias    = (const float*)d_in[3];
    float*       out     = (float*)d_out;

    static int attr_set = 0;
    if (!attr_set) {
        cudaFuncSetAttribute(il_main, cudaFuncAttributeMaxDynamicSharedMemorySize, RING_B);
        attr_set = 1;
    }

    // prep: 4,194,304 elems / 4 per thread / 256 per block = 4096 blocks
    il_prep<<<4096, NTHREADS>>>(table, bias, out);

    dim3 grid(BATCH / BT, ISPLIT);   // 16 x 37 = 592 CTAs = 148 SMs * 4
    il_main<<<grid, NTHREADS, RING_B>>>(x, indices, out);
}

// round 16
// speedup vs baseline: 1.7777x; 1.0767x over previous
#include <cuda_runtime.h>
#include <cuda_fp16.h>
#include <cstdint>

#define BATCH     512
#define SIZE_IN   1024
#define SIZE_OUT  256
#define NQ        16

#define BT        32                 // batch tile per CTA
#define ISPLIT    37                 // 16 * 37 = 592 = 148 SMs * 4 CTAs exactly
#define NPHMAX    14                 // ceil(28/2)
#define NTHREADS  512
#define SLOT_B    16384              // bytes per slot: 2 features x 16 rows x 512 B fp16
#define RING_B    (2 * SLOT_B)       // 32 KB dynamic smem (double buffer)

// fp16 copy of the weight table (8 MB static scratch; no allocation allowed)
__device__ __half g_tableh[NQ * SIZE_IN * SIZE_OUT];

// Fused prep: table fp32 -> fp16, 4 elems/thread (1 LDG.128 + 1 STG.64),
// 1M threads for MLP; first 512 blocks also write out[b,:] = bias.
__global__ void il_prep(const float* __restrict__ table,
                        const float* __restrict__ bias,
                        float* __restrict__ out) {
    const size_t i = ((size_t)blockIdx.x * 256 + threadIdx.x) * 4;
    const float4 a = *reinterpret_cast<const float4*>(table + i);
    __half2 h[2];
    h[0] = __floats2half2_rn(a.x, a.y);
    h[1] = __floats2half2_rn(a.z, a.w);
    *reinterpret_cast<uint2*>(g_tableh + i) = *reinterpret_cast<uint2*>(h);

    if (blockIdx.x < BATCH) {   // out[b, o] = bias[o]
        out[blockIdx.x * SIZE_OUT + threadIdx.x] = bias[threadIdx.x];
    }
}

__device__ __forceinline__ void cp_async16(uint32_t saddr, const void* gptr) {
    asm volatile("cp.async.cg.shared.global [%0], [%1], 16;\n" :: "r"(saddr), "l"(gptr));
}
__device__ __forceinline__ void cp_commit() {
    asm volatile("cp.async.commit_group;\n" ::: "memory");
}
__device__ __forceinline__ void red_v4(float* p, float a, float b, float c, float d) {
    asm volatile("red.global.add.v4.f32 [%0], {%1, %2, %3, %4};"
                 :: "l"(p), "f"(a), "f"(b), "f"(c), "f"(d) : "memory");
}

// One CTA: 32 batches x (27..28) features x 256 outputs, fp16 weights,
// 512 threads @ <=32 regs -> 4 CTAs/SM = 64 warps/SM for latency hiding.
// 2 batches x 8 outputs per thread; double-buffered 2-feature phases.
__global__ __launch_bounds__(NTHREADS, 4)
void il_main(const float* __restrict__ x,
             const int* __restrict__ indices,   // JAX canonicalizes int64 -> int32
             float* __restrict__ out) {
    extern __shared__ __align__(16) __half sW[];   // 2 x 8192 halves (32 KB)
    __shared__ float4 sxq[BT][NPHMAX];   // {x0, bits(q0*256), x1, bits(q1*256)}

    const int b0  = blockIdx.x * BT;
    const int lo  = (int)(((long long)blockIdx.y * SIZE_IN) / ISPLIT);
    const int hi  = (int)(((long long)(blockIdx.y + 1) * SIZE_IN) / ISPLIT);
    const int len = hi - lo;             // 27 or 28
    const int nph = (len + 1) >> 1;      // 14
    const int t   = threadIdx.x;
    const int og  = t & 31;              // output columns og*8 .. og*8+7
    const int bg  = t >> 5;              // batches bg*2, bg*2+1 (warp-uniform)

    const uint32_t sW_u32 = (uint32_t)__cvta_generic_to_shared(sW);

    // Staging map: 16 KB/phase = 1024 x 16B segs; thread covers segs t, t+512.
    // seg -> feature f = seg>>9, row q = (seg>>5)&15, chunk c = seg&31.
    const uint32_t off0 = (uint32_t)(((t >> 5) & 15) * 512 + (t & 31) * 16);       // f=0
    const uint32_t off1 = 8192u + off0;                                            // f=1 (seg+512)
    const __half* sb0 = g_tableh + ((size_t)((t >> 5) & 15) * SIZE_IN) * SIZE_OUT + (t & 31) * 8;

    // Prefetch phase 0 into buffer 0 (one commit group).
    {
        cp_async16(sW_u32 + off0, sb0 + (size_t)lo * SIZE_OUT);
        if (lo + 1 < hi) cp_async16(sW_u32 + off1, sb0 + (size_t)(lo + 1) * SIZE_OUT);
        cp_commit();
    }

    // Preload sxq: thread covers batch bl = t>>4, phase p = t&15.
    {
        const int bl = t >> 4;
        const int p  = t & 15;
        if (p < nph) {
            const float* xp = x       + (size_t)(b0 + bl) * SIZE_IN;
            const int*   qp = indices + (size_t)(b0 + bl) * SIZE_IN;
            const int i0 = lo + 2 * p;
            float4 v;
            v.x = xp[i0];
            v.y = __int_as_float(qp[i0] * SIZE_OUT);
            if (i0 + 1 < hi) {
                v.z = xp[i0 + 1];
                v.w = __int_as_float(qp[i0 + 1] * SIZE_OUT);
            } else {
                v.z = 0.f;
                v.w = __int_as_float(0);
            }
            sxq[bl][p] = v;
        }
    }

    float acc[2][8];
    #pragma unroll
    for (int bl = 0; bl < 2; bl++)
        #pragma unroll
        for (int c = 0; c < 8; c++) acc[bl][c] = 0.f;

    for (int p = 0; p < nph; p++) {
        const int buf = p & 1;

        asm volatile("cp.async.wait_group 0;" ::: "memory");
        __syncthreads();   // staged data visible; all readers done with buf^1

        // Prefetch phase p+1 into the other buffer.
        if (p + 1 < nph) {
            const int i0 = lo + 2 * (p + 1);
            const uint32_t dst = sW_u32 + (uint32_t)((buf ^ 1) * SLOT_B);
            cp_async16(dst + off0, sb0 + (size_t)i0 * SIZE_OUT);
            if (i0 + 1 < hi) cp_async16(dst + off1, sb0 + (size_t)(i0 + 1) * SIZE_OUT);
            cp_commit();
        }

        const __half* wb  = sW + buf * 8192;
        const bool    two = (2 * p + 1 < len);

        #pragma unroll
        for (int bl = 0; bl < 2; bl++) {
            const float4 v = sxq[bg * 2 + bl][p];   // 16B broadcast
            // feature 0
            {
                const uint4 u = *reinterpret_cast<const uint4*>(
                    wb + __float_as_int(v.y) + og * 8);
                const __half2* hp = reinterpret_cast<const __half2*>(&u);
                #pragma unroll
                for (int q = 0; q < 4; q++) {
                    const float2 f = __half22float2(hp[q]);
                    acc[bl][q * 2 + 0] += v.x * f.x;
                    acc[bl][q * 2 + 1] += v.x * f.y;
                }
            }
            // feature 1
            if (two) {
                const uint4 u = *reinterpret_cast<const uint4*>(
                    wb + 4096 + __float_as_int(v.w) + og * 8);
                const __half2* hp = reinterpret_cast<const __half2*>(&u);
                #pragma unroll
                for (int q = 0; q < 4; q++) {
                    const float2 f = __half22float2(hp[q]);
                    acc[bl][q * 2 + 0] += v.z * f.x;
                    acc[bl][q * 2 + 1] += v.z * f.y;
                }
            }
        }
    }

    // Combine split-k partials: 2 vectorized reductions per batch.
    #pragma unroll
    for (int bl = 0; bl < 2; bl++) {
        const int b = b0 + bg * 2 + bl;
        float* op = out + (size_t)b * SIZE_OUT + og * 8;
        red_v4(op,     acc[bl][0], acc[bl][1], acc[bl][2], acc[bl][3]);
        red_v4(op + 4, acc[bl][4], acc[bl][5], acc[bl][6], acc[bl][7]);
    }
}

extern "C" void kernel_launch(void* const* d_in, const int* in_sizes, int n_in,
                              void* d_out, int out_size) {
    const float* x       = (const float*)d_in[0];
    const int*   indices = (const int*)d_in[1];
    const float* table   = (const float*)d_in[2];
    const float* bias    = (const float*)d_in[3];
    float*       out     = (float*)d_out;

    static int attr_set = 0;
    if (!attr_set) {
        cudaFuncSetAttribute(il_main, cudaFuncAttributeMaxDynamicSharedMemorySize, RING_B);
        attr_set = 1;
    }

    // prep: 4,194,304 elems / 4 per thread / 256 per block = 4096 blocks
    il_prep<<<4096, 256>>>(table, bias, out);

    dim3 grid(BATCH / BT, ISPLIT);   // 16 x 37 = 592 CTAs = 148 SMs * 4
    il_main<<<grid, NTHREADS, RING_B>>>(x, indices, out);
}